// round 3
// baseline (speedup 1.0000x reference)
#include <cuda_runtime.h>

static constexpr int K = 32;
static constexpr int ROWS_PER_THREAD = 8;   // 2 x float4 output stores per plane
static constexpr int THREADS = 256;

__global__ __launch_bounds__(THREADS, 3)
void bignet_kernel(const float4* __restrict__ x4,
                   const float4* __restrict__ W4,   // [K] float4
                   const float*  __restrict__ b,    // [K]
                   float* __restrict__ out,         // [K, N]
                   int N)
{
    __shared__ float4 sW[K];
    __shared__ float  sb[K];
    if (threadIdx.x < K) {
        sW[threadIdx.x] = W4[threadIdx.x];
        sb[threadIdx.x] = b[threadIdx.x];
    }
    __syncthreads();

    int t  = blockIdx.x * blockDim.x + threadIdx.x;
    int n0 = t * ROWS_PER_THREAD;
    if (n0 >= N) return;

    if (n0 + ROWS_PER_THREAD <= N) {
        // 8 full rows: 128B contiguous load per thread, read-once.
        float4 r[ROWS_PER_THREAD];
        #pragma unroll
        for (int i = 0; i < ROWS_PER_THREAD; i++)
            r[i] = __ldcs(&x4[n0 + i]);

        float* outp = out + n0;

        #pragma unroll 4
        for (int k = 0; k < K; k++) {
            float4 w  = sW[k];
            float  bb = sb[k];
            float4 o0, o1;
            o0.x = fmaf(r[0].x, w.x, fmaf(r[0].y, w.y, fmaf(r[0].z, w.z, fmaf(r[0].w, w.w, bb))));
            o0.y = fmaf(r[1].x, w.x, fmaf(r[1].y, w.y, fmaf(r[1].z, w.z, fmaf(r[1].w, w.w, bb))));
            o0.z = fmaf(r[2].x, w.x, fmaf(r[2].y, w.y, fmaf(r[2].z, w.z, fmaf(r[2].w, w.w, bb))));
            o0.w = fmaf(r[3].x, w.x, fmaf(r[3].y, w.y, fmaf(r[3].z, w.z, fmaf(r[3].w, w.w, bb))));
            o1.x = fmaf(r[4].x, w.x, fmaf(r[4].y, w.y, fmaf(r[4].z, w.z, fmaf(r[4].w, w.w, bb))));
            o1.y = fmaf(r[5].x, w.x, fmaf(r[5].y, w.y, fmaf(r[5].z, w.z, fmaf(r[5].w, w.w, bb))));
            o1.z = fmaf(r[6].x, w.x, fmaf(r[6].y, w.y, fmaf(r[6].z, w.z, fmaf(r[6].w, w.w, bb))));
            o1.w = fmaf(r[7].x, w.x, fmaf(r[7].y, w.y, fmaf(r[7].z, w.z, fmaf(r[7].w, w.w, bb))));
            float* p = outp + (size_t)k * N;
            __stcs(reinterpret_cast<float4*>(p),     o0);
            __stcs(reinterpret_cast<float4*>(p + 4), o1);
        }
    } else {
        // Tail path: per-row scalar stores.
        for (int rr = 0; rr < ROWS_PER_THREAD; rr++) {
            int n = n0 + rr;
            if (n >= N) break;
            float4 xr = __ldcs(&x4[n]);
            #pragma unroll
            for (int k = 0; k < K; k++) {
                float4 w  = sW[k];
                float  bb = sb[k];
                float  o  = fmaf(xr.x, w.x, fmaf(xr.y, w.y, fmaf(xr.z, w.z, fmaf(xr.w, w.w, bb))));
                out[(size_t)k * N + n] = o;
            }
        }
    }
}

extern "C" void kernel_launch(void* const* d_in, const int* in_sizes, int n_in,
                              void* d_out, int out_size)
{
    const float* x = (const float*)d_in[0];   // [N, 4]
    const float* W = (const float*)d_in[1];   // [K, 1, 4]
    const float* b = (const float*)d_in[2];   // [K, 1]
    float* out = (float*)d_out;               // [K, N, 1]

    int N = in_sizes[0] / 4;

    int threads_needed = (N + ROWS_PER_THREAD - 1) / ROWS_PER_THREAD;
    int blocks = (threads_needed + THREADS - 1) / THREADS;

    bignet_kernel<<<blocks, THREADS>>>(
        (const float4*)x, (const float4*)W, b, out, N);
}

// round 4
// speedup vs baseline: 1.3050x; 1.3050x over previous
#include <cuda_runtime.h>

static constexpr int K = 32;
static constexpr int ROWS_PER_THREAD = 4;
static constexpr int THREADS = 256;
static constexpr int ROWS_PER_TILE = THREADS * ROWS_PER_THREAD;  // 1024
static constexpr int GRID = 148 * 4;  // persistent: one full wave at 4 CTAs/SM

__global__ __launch_bounds__(THREADS, 4)
void bignet_kernel(const float4* __restrict__ x4,
                   const float4* __restrict__ W4,   // [K] float4
                   const float*  __restrict__ b,    // [K]
                   float* __restrict__ out,         // [K, N]
                   int N, int numTiles)
{
    __shared__ float4 sW[K];
    __shared__ float  sb[K];
    if (threadIdx.x < K) {
        sW[threadIdx.x] = W4[threadIdx.x];
        sb[threadIdx.x] = b[threadIdx.x];
    }
    __syncthreads();

    for (int tile = blockIdx.x; tile < numTiles; tile += gridDim.x) {
        int n0 = tile * ROWS_PER_TILE + threadIdx.x * ROWS_PER_THREAD;
        if (n0 >= N) continue;

        if (n0 + ROWS_PER_THREAD <= N) {
            float4 r0 = __ldcs(&x4[n0 + 0]);
            float4 r1 = __ldcs(&x4[n0 + 1]);
            float4 r2 = __ldcs(&x4[n0 + 2]);
            float4 r3 = __ldcs(&x4[n0 + 3]);

            float* outp = out + n0;

            #pragma unroll 8
            for (int k = 0; k < K; k++) {
                float4 w  = sW[k];
                float  bb = sb[k];
                float4 o;
                o.x = fmaf(r0.x, w.x, fmaf(r0.y, w.y, fmaf(r0.z, w.z, fmaf(r0.w, w.w, bb))));
                o.y = fmaf(r1.x, w.x, fmaf(r1.y, w.y, fmaf(r1.z, w.z, fmaf(r1.w, w.w, bb))));
                o.z = fmaf(r2.x, w.x, fmaf(r2.y, w.y, fmaf(r2.z, w.z, fmaf(r2.w, w.w, bb))));
                o.w = fmaf(r3.x, w.x, fmaf(r3.y, w.y, fmaf(r3.z, w.z, fmaf(r3.w, w.w, bb))));
                *reinterpret_cast<float4*>(outp + (size_t)k * N) = o;
            }
        } else {
            // Tail: per-row scalar stores.
            for (int rr = 0; rr < ROWS_PER_THREAD; rr++) {
                int n = n0 + rr;
                if (n >= N) break;
                float4 xr = __ldcs(&x4[n]);
                #pragma unroll
                for (int k = 0; k < K; k++) {
                    float4 w  = sW[k];
                    float  bb = sb[k];
                    float  o  = fmaf(xr.x, w.x, fmaf(xr.y, w.y, fmaf(xr.z, w.z, fmaf(xr.w, w.w, bb))));
                    out[(size_t)k * N + n] = o;
                }
            }
        }
    }
}

extern "C" void kernel_launch(void* const* d_in, const int* in_sizes, int n_in,
                              void* d_out, int out_size)
{
    const float* x = (const float*)d_in[0];   // [N, 4]
    const float* W = (const float*)d_in[1];   // [K, 1, 4]
    const float* b = (const float*)d_in[2];   // [K, 1]
    float* out = (float*)d_out;               // [K, N, 1]

    int N = in_sizes[0] / 4;
    int numTiles = (N + ROWS_PER_TILE - 1) / ROWS_PER_TILE;

    int blocks = GRID < numTiles ? GRID : numTiles;

    bignet_kernel<<<blocks, THREADS>>>(
        (const float4*)x, (const float4*)W, b, out, N, numTiles);
}

// round 5
// speedup vs baseline: 1.4346x; 1.0994x over previous
#include <cuda_runtime.h>

static constexpr int K = 32;
static constexpr int ROWS_PER_THREAD = 4;
static constexpr int THREADS = 256;

__global__ __launch_bounds__(THREADS, 4)
void bignet_kernel(const float4* __restrict__ x4,
                   const float4* __restrict__ W4,   // [K] float4
                   const float*  __restrict__ b,    // [K]
                   float* __restrict__ out,         // [K, N]
                   int N)
{
    __shared__ float4 sW[K];
    __shared__ float  sb[K];
    if (threadIdx.x < K) {
        sW[threadIdx.x] = W4[threadIdx.x];
        sb[threadIdx.x] = b[threadIdx.x];
    }
    __syncthreads();

    int t  = blockIdx.x * blockDim.x + threadIdx.x;
    int n0 = t * ROWS_PER_THREAD;
    if (n0 >= N) return;

    // Decorrelate plane order across CTAs so the chip's store streams are
    // spread over all 32 output planes at any instant (DRAM bank/page spread).
    int rot = blockIdx.x & (K - 1);

    if (n0 + ROWS_PER_THREAD <= N) {
        float4 r0 = __ldcs(&x4[n0 + 0]);
        float4 r1 = __ldcs(&x4[n0 + 1]);
        float4 r2 = __ldcs(&x4[n0 + 2]);
        float4 r3 = __ldcs(&x4[n0 + 3]);

        float* outp = out + n0;

        #pragma unroll 8
        for (int k = 0; k < K; k++) {
            int kk = (k + rot) & (K - 1);
            float4 w  = sW[kk];
            float  bb = sb[kk];
            float4 o;
            o.x = fmaf(r0.x, w.x, fmaf(r0.y, w.y, fmaf(r0.z, w.z, fmaf(r0.w, w.w, bb))));
            o.y = fmaf(r1.x, w.x, fmaf(r1.y, w.y, fmaf(r1.z, w.z, fmaf(r1.w, w.w, bb))));
            o.z = fmaf(r2.x, w.x, fmaf(r2.y, w.y, fmaf(r2.z, w.z, fmaf(r2.w, w.w, bb))));
            o.w = fmaf(r3.x, w.x, fmaf(r3.y, w.y, fmaf(r3.z, w.z, fmaf(r3.w, w.w, bb))));
            *reinterpret_cast<float4*>(outp + (size_t)kk * N) = o;
        }
    } else {
        // Tail path: per-row scalar stores.
        for (int rr = 0; rr < ROWS_PER_THREAD; rr++) {
            int n = n0 + rr;
            if (n >= N) break;
            float4 xr = __ldcs(&x4[n]);
            #pragma unroll
            for (int k = 0; k < K; k++) {
                float4 w  = sW[k];
                float  bb = sb[k];
                float  o  = fmaf(xr.x, w.x, fmaf(xr.y, w.y, fmaf(xr.z, w.z, fmaf(xr.w, w.w, bb))));
                out[(size_t)k * N + n] = o;
            }
        }
    }
}

extern "C" void kernel_launch(void* const* d_in, const int* in_sizes, int n_in,
                              void* d_out, int out_size)
{
    const float* x = (const float*)d_in[0];   // [N, 4]
    const float* W = (const float*)d_in[1];   // [K, 1, 4]
    const float* b = (const float*)d_in[2];   // [K, 1]
    float* out = (float*)d_out;               // [K, N, 1]

    int N = in_sizes[0] / 4;

    int threads_needed = (N + ROWS_PER_THREAD - 1) / ROWS_PER_THREAD;
    int blocks = (threads_needed + THREADS - 1) / THREADS;

    bignet_kernel<<<blocks, THREADS>>>(
        (const float4*)x, (const float4*)W, b, out, N);
}

// round 6
// speedup vs baseline: 1.4429x; 1.0058x over previous
#include <cuda_runtime.h>

static constexpr int K = 32;
static constexpr int ROWS_PER_THREAD = 4;
static constexpr int THREADS = 256;

__global__ __launch_bounds__(THREADS, 4)
void bignet_kernel(const float4* __restrict__ x4,
                   const float4* __restrict__ W4,   // [K] float4
                   const float*  __restrict__ b,    // [K]
                   float* __restrict__ out,         // [K, N]
                   int N)
{
    __shared__ float4 sW[K];
    __shared__ float  sb[K];
    if (threadIdx.x < K) {
        sW[threadIdx.x] = W4[threadIdx.x];
        sb[threadIdx.x] = b[threadIdx.x];
    }
    __syncthreads();

    int t  = blockIdx.x * blockDim.x + threadIdx.x;
    int n0 = t * ROWS_PER_THREAD;
    if (n0 >= N) return;

    // Warp-granular plane rotation: spread concurrent store streams across
    // all 32 output planes (DRAM page/bank + L2-partition decorrelation).
    int rot = ((blockIdx.x << 3) + (threadIdx.x >> 5)) & (K - 1);

    if (n0 + ROWS_PER_THREAD <= N) {
        float4 r0 = __ldcs(&x4[n0 + 0]);
        float4 r1 = __ldcs(&x4[n0 + 1]);
        float4 r2 = __ldcs(&x4[n0 + 2]);
        float4 r3 = __ldcs(&x4[n0 + 3]);

        // Running output pointer: starts at plane `rot`, advances by one plane
        // per iteration, wraps once. Avoids per-iteration 64-bit IMADs.
        float* p = out + (size_t)rot * N + n0;
        float* const pend = out + (size_t)K * N + n0;  // wrap sentinel
        const size_t planeStride = (size_t)N;
        const size_t wrapBack = (size_t)K * N;

        #pragma unroll 8
        for (int k = 0; k < K; k++) {
            int kk = (k + rot) & (K - 1);
            float4 w  = sW[kk];
            float  bb = sb[kk];
            float4 o;
            o.x = fmaf(r0.x, w.x, fmaf(r0.y, w.y, fmaf(r0.z, w.z, fmaf(r0.w, w.w, bb))));
            o.y = fmaf(r1.x, w.x, fmaf(r1.y, w.y, fmaf(r1.z, w.z, fmaf(r1.w, w.w, bb))));
            o.z = fmaf(r2.x, w.x, fmaf(r2.y, w.y, fmaf(r2.z, w.z, fmaf(r2.w, w.w, bb))));
            o.w = fmaf(r3.x, w.x, fmaf(r3.y, w.y, fmaf(r3.z, w.z, fmaf(r3.w, w.w, bb))));
            *reinterpret_cast<float4*>(p) = o;
            p += planeStride;
            if (p >= pend) p -= wrapBack;
        }
    } else {
        // Tail path: per-row scalar stores.
        for (int rr = 0; rr < ROWS_PER_THREAD; rr++) {
            int n = n0 + rr;
            if (n >= N) break;
            float4 xr = __ldcs(&x4[n]);
            #pragma unroll
            for (int k = 0; k < K; k++) {
                float4 w  = sW[k];
                float  bb = sb[k];
                float  o  = fmaf(xr.x, w.x, fmaf(xr.y, w.y, fmaf(xr.z, w.z, fmaf(xr.w, w.w, bb))));
                out[(size_t)k * N + n] = o;
            }
        }
    }
}

extern "C" void kernel_launch(void* const* d_in, const int* in_sizes, int n_in,
                              void* d_out, int out_size)
{
    const float* x = (const float*)d_in[0];   // [N, 4]
    const float* W = (const float*)d_in[1];   // [K, 1, 4]
    const float* b = (const float*)d_in[2];   // [K, 1]
    float* out = (float*)d_out;               // [K, N, 1]

    int N = in_sizes[0] / 4;

    int threads_needed = (N + ROWS_PER_THREAD - 1) / ROWS_PER_THREAD;
    int blocks = (threads_needed + THREADS - 1) / THREADS;

    bignet_kernel<<<blocks, THREADS>>>(
        (const float4*)x, (const float4*)W, b, out, N);
}